// round 8
// baseline (speedup 1.0000x reference)
#include <cuda_runtime.h>

#define BDIM 8
#define FDIM 64
#define NROWS (BDIM * BDIM * FDIM)     // 4096
#define ROWS_PER_BLK 8
#define NBLK (NROWS / ROWS_PER_BLK)    // 512
#define BLKT (ROWS_PER_BLK * FDIM)     // 512 threads

// per-block partials (plain stores, no contention) + completion counter
__device__ float        g_part[NBLK];
__device__ unsigned int g_cnt = 0u;

__global__ __launch_bounds__(BLKT) void ap_kernel(
    const float* __restrict__ sim,
    const float* __restrict__ pos,
    const float* __restrict__ neg,
    const float* __restrict__ label,
    float* __restrict__ out)
{
    __shared__ float sP [ROWS_PER_BLK][FDIM];
    __shared__ float sN0[ROWS_PER_BLK][FDIM];
    __shared__ int   cP [ROWS_PER_BLK][2], cN[ROWS_PER_BLK][2];
    __shared__ float wsum[ROWS_PER_BLK * 2];
    __shared__ bool  s_last;
    __shared__ float s_red[16];

    const int tid  = threadIdx.x;
    const int r    = tid >> 6;          // row within block (0..7)
    const int half = (tid >> 5) & 1;    // which 32-lane half of the row
    const int lane = tid & 31;
    const int row  = blockIdx.x * ROWS_PER_BLK + r;
    const int base = row * FDIM + (tid & 63);

    const float v    = sim[base];
    const bool  isP  = (pos[base] != 0.0f);
    const bool  isN0 = (!isP) && (neg[base] != 0.0f);

    const unsigned mP = __ballot_sync(0xffffffffu, isP);
    const unsigned mN = __ballot_sync(0xffffffffu, isN0);
    if (lane == 0) { cP[r][half] = __popc(mP); cN[r][half] = __popc(mN); }
    __syncthreads();

    const unsigned lt = (1u << lane) - 1u;
    const int offP = (half ? cP[r][0] : 0) + __popc(mP & lt);
    const int offN = (half ? cN[r][0] : 0) + __popc(mN & lt);
    if (isP)  sP [r][offP] = v;
    if (isN0) sN0[r][offN] = v;
    const int nP  = cP[r][0] + cP[r][1];
    const int nN0 = cN[r][0] + cN[r][1];
    __syncthreads();

    float ratio = 0.0f;
    if (isP) {
        const float sj = v;
        int cnt = 0;
        #pragma unroll 4
        for (int m = 0; m < nP; m++)
            cnt += (sP[r][m] > sj) ? 1 : 0;

        float qs = 0.0f;
        #pragma unroll 4
        for (int m = 0; m < nN0; m++) {
            float t = (sN0[r][m] - sj) * 10.0f;   // x / sigma
            float u = t + 1.0f;
            float w = fmaxf(u, 0.0f);
            qs += (t > 0.0f) ? (u + t) : (w * w); // 2t+1 | (t+1)^2 | 0
        }
        float prk = 1.0f + 10.0f * (float)cnt;
        ratio = prk / (prk + qs);
    }

    // ratio / nP folded in before the warp reduction (nP>0 guaranteed when isP)
    if (isP) ratio /= (float)nP;

    #pragma unroll
    for (int s = 16; s > 0; s >>= 1)
        ratio += __shfl_down_sync(0xffffffffu, ratio, s);
    if (lane == 0) wsum[tid >> 5] = ratio;
    __syncthreads();

    if (tid == 0) {
        // all 8 rows of this block share one (b1,b2) pair
        float bs = 0.0f;
        #pragma unroll
        for (int i = 0; i < 2 * ROWS_PER_BLK; i++) bs += wsum[i];
        bs *= label[blockIdx.x >> 3] * (1.0f / (float)FDIM);
        g_part[blockIdx.x] = bs;              // uncontended store
        __threadfence();
        unsigned done = atomicAdd(&g_cnt, 1u);
        s_last = (done == (unsigned)(gridDim.x - 1));
    }
    __syncthreads();

    if (s_last) {
        // last block reduces 512 partials in fixed order -> deterministic
        float p = __ldcg(&g_part[tid]);       // one element per thread (NBLK == BLKT)
        #pragma unroll
        for (int s = 16; s > 0; s >>= 1)
            p += __shfl_down_sync(0xffffffffu, p, s);
        if (lane == 0) s_red[tid >> 5] = p;
        __syncthreads();
        if (tid == 0) {
            float ap = 0.0f;
            #pragma unroll
            for (int i = 0; i < 16; i++) ap += s_red[i];
            float den = 0.0f;
            #pragma unroll
            for (int i = 0; i < BDIM * BDIM; i++) den += label[i];
            out[0] = 1.0f - ap / den;
            atomicExch(&g_cnt, 0u);           // reset for next graph replay
        }
    }
}

extern "C" void kernel_launch(void* const* d_in, const int* in_sizes, int n_in,
                              void* d_out, int out_size)
{
    const float* sim   = (const float*)d_in[0];
    const float* pos   = (const float*)d_in[1];
    const float* neg   = (const float*)d_in[2];
    const float* label = (const float*)d_in[3];
    float* out = (float*)d_out;

    ap_kernel<<<NBLK, BLKT>>>(sim, pos, neg, label, out);
}